// round 8
// baseline (speedup 1.0000x reference)
#include <cuda_runtime.h>
#include <cstdint>

// ---------------------------------------------------------------------------
// Block-diagonal linear (256x0e+256x1o+256x2e): 3 GEMMs over rows (z,i):
//   A'[z*D+i][u] = feat[z, XOFF + u*D + i];  C = A' * W_b / 16.
// R8: fragment-order smem for A and B (tf32 converted at staging time),
// inner loop = pure LDS.128 + HMMA. 256-thr CTAs, 2 CTAs/SM, tile 128x128,
// warp tile 32x64, one barrier per k-chunk, B register-prefetched 1 chunk.
// mma.sync m16n8k8 tf32 (PTX targets compute_103; tcgen05 unavailable).
// ---------------------------------------------------------------------------
#define HX_BZ   50000
#define HX_FEAT 2304

static constexpr int NTH   = 256;
static constexpr int STAGE = 32768;          // A 16KB + B 16KB per stage
static constexpr int SMEMB = 2 * STAGE;      // 65536

// ---------------------------------------------------------------------------
__device__ __forceinline__ uint32_t f2tf(float x) {
    uint32_t r;
    asm("cvt.rna.tf32.f32 %0, %1;" : "=r"(r) : "f"(x));
    return r;
}

__device__ __forceinline__ void mma8(float* c, const uint32_t* a,
                                     uint32_t b0, uint32_t b1) {
    asm volatile(
        "mma.sync.aligned.m16n8k8.row.col.f32.tf32.tf32.f32 "
        "{%0,%1,%2,%3}, {%4,%5,%6,%7}, {%8,%9}, {%0,%1,%2,%3};"
        : "+f"(c[0]), "+f"(c[1]), "+f"(c[2]), "+f"(c[3])
        : "r"(a[0]), "r"(a[1]), "r"(a[2]), "r"(a[3]), "r"(b0), "r"(b1));
}

// ---------------------------------------------------------------------------
template<int D, int XOFF, int WOFF, int MTOT>
__global__ void __launch_bounds__(NTH, 2)
lin_k(const float* __restrict__ feat, const float* __restrict__ wt,
      float* __restrict__ out)
{
    constexpr int F4Z  = 8 * D;                       // float4 per z per chunk
    constexpr int NZ   = (D == 1) ? 128 : (D == 3) ? 44 : 27;
    constexpr int TOT4 = NZ * F4Z;
    constexpr int PA   = (TOT4 + NTH - 1) / NTH;      // 4 / 5 / 5

    extern __shared__ char smem[];

    const int tid  = threadIdx.x;
    const int lane = tid & 31;
    const int wid  = tid >> 5;
    const int g    = lane >> 2;
    const int tg   = lane & 3;
    const int wm   = wid >> 1;     // 4 x 32 rows
    const int wn   = wid & 1;      // 2 x 64 cols

    const int bid  = blockIdx.x;
    const int tile = bid >> 1;
    const int nh   = bid & 1;
    const int m0   = tile * 128;
    const int z0   = m0 / D;
    const int ro   = m0 - z0 * D;

    // ---- A staging precompute: PA float4 per thread, packed STS indices ----
    uint32_t a_goff[PA];           // byte offset into feat (chunk 0)
    bool     a_ld[PA];
    uint32_t a_pk[PA][2];          // 4 x (valid<<15 | fidx[12b]) per float4
    #pragma unroll
    for (int p = 0; p < PA; p++) {
        const int e    = tid + NTH * p;
        const int zrel = e / F4Z;
        const int q    = e - zrel * F4Z;
        const int z    = z0 + zrel;
        a_ld[p]   = (e < TOT4) && (z < HX_BZ);
        a_goff[p] = (uint32_t)((z * HX_FEAT + XOFF + q * 4) * 4);
        uint32_t pk[2] = {0u, 0u};
        #pragma unroll
        for (int j = 0; j < 4; j++) {
            const int pos = q * 4 + j;
            const int k   = pos / D;
            const int i   = pos - k * D;
            const int row = zrel * D + i - ro;
            uint32_t u = 0;
            if (e < TOT4 && (unsigned)row < 128u) {
                const int s  = k >> 3, ktg = k & 3, kh = (k >> 2) & 1;
                const int rb = row >> 4, gg = row & 7, hf = (row >> 3) & 1;
                const int ib = ((gg << 2) | ktg) ^ (5 * s);
                const int fidx = (((s * 8 + rb) * 32 + ib) << 2) + hf + 2 * kh;
                u = 0x8000u | (uint32_t)fidx;
            }
            pk[j >> 1] |= u << ((j & 1) * 16);
        }
        a_pk[p][0] = pk[0];
        a_pk[p][1] = pk[1];
    }

    // ---- B staging precompute: 4 frag-uint4 per thread ----
    uint32_t b_goff[4];            // float offset within (WOFF + nh*128) block
    #pragma unroll
    for (int p = 0; p < 4; p++) {
        const int e     = tid + NTH * p;
        const int block = e >> 5;
        const int l5    = e & 31;
        const int gg    = l5 >> 2, tt = l5 & 3;
        const int nfp   = block & 3;
        const int wnn   = (block >> 2) & 1;
        const int s     = block >> 3;
        const int k     = 8 * s + tt;
        const int n     = wnn * 64 + nfp * 16 + gg;
        b_goff[p] = (uint32_t)(k * 256 + n);
    }

    float rB[4][4];

    auto ldgB = [&](int ch) {
        const float* wp = wt + WOFF + nh * 128 + (size_t)ch * 32 * 256;
        #pragma unroll
        for (int p = 0; p < 4; p++) {
            const float* s = wp + b_goff[p];
            rB[p][0] = s[0];
            rB[p][1] = s[1024];     // k+4
            rB[p][2] = s[8];        // n+8
            rB[p][3] = s[1032];
        }
    };

    auto stsB = [&](int st) {
        uint4* Bs = (uint4*)(smem + st * STAGE + 16384);
        #pragma unroll
        for (int p = 0; p < 4; p++) {
            uint4 q;
            q.x = f2tf(rB[p][0]); q.y = f2tf(rB[p][1]);
            q.z = f2tf(rB[p][2]); q.w = f2tf(rB[p][3]);
            Bs[tid + NTH * p] = q;
        }
    };

    auto stageA = [&](int ch, int st) {
        uint32_t* As = (uint32_t*)(smem + st * STAGE);
        float4 v[PA];
        #pragma unroll
        for (int p = 0; p < PA; p++)
            if (a_ld[p])
                v[p] = *(const float4*)((const char*)feat + a_goff[p]
                                        + (uint32_t)ch * (32 * D * 4));
        #pragma unroll
        for (int p = 0; p < PA; p++) {
            const float vv[4] = {v[p].x, v[p].y, v[p].z, v[p].w};
            #pragma unroll
            for (int j = 0; j < 4; j++) {
                const uint32_t u = (a_pk[p][j >> 1] >> ((j & 1) * 16)) & 0xFFFFu;
                if (u & 0x8000u) As[u & 0xFFFu] = f2tf(vv[j]);
            }
        }
    };

    // ---- accumulators ----
    float c[2][8][4];
    #pragma unroll
    for (int mf = 0; mf < 2; mf++)
        #pragma unroll
        for (int nf = 0; nf < 8; nf++)
            #pragma unroll
            for (int q = 0; q < 4; q++) c[mf][nf][q] = 0.0f;

    auto compute = [&](int st) {
        const char* Ab = smem + st * STAGE;
        const uint4* Bs = (const uint4*)(smem + st * STAGE + 16384);
        #pragma unroll
        for (int s = 0; s < 4; s++) {
            const int ib = lane ^ (5 * s);
            uint4 a0 = *(const uint4*)(Ab + ((s * 8 + wm * 2 + 0) * 32 + ib) * 16);
            uint4 a1 = *(const uint4*)(Ab + ((s * 8 + wm * 2 + 1) * 32 + ib) * 16);
            #pragma unroll
            for (int nfp = 0; nfp < 4; nfp++) {
                const uint4 b = Bs[((s * 2 + wn) * 4 + nfp) * 32 + lane];
                mma8(c[0][2 * nfp],     (const uint32_t*)&a0, b.x, b.y);
                mma8(c[1][2 * nfp],     (const uint32_t*)&a1, b.x, b.y);
                mma8(c[0][2 * nfp + 1], (const uint32_t*)&a0, b.z, b.w);
                mma8(c[1][2 * nfp + 1], (const uint32_t*)&a1, b.z, b.w);
            }
        }
    };

    // ---- pipeline: B prefetched 1 chunk in regs; A staged post-compute ----
    ldgB(0);
    stsB(0);
    stageA(0, 0);
    __syncthreads();
    ldgB(1);

    #pragma unroll 1
    for (int ch = 0; ch < 8; ch++) {
        compute(ch & 1);
        if (ch < 7) {
            stsB((ch + 1) & 1);             // frees rB before stageA peak
            stageA(ch + 1, (ch + 1) & 1);
            __syncthreads();
            if (ch < 6) ldgB(ch + 2);
        }
    }

    // ---- epilogue: scatter rows (z,i), scale 1/sqrt(256) ----
    const float S = 0.0625f;
    #pragma unroll
    for (int mf = 0; mf < 2; mf++) {
        #pragma unroll
        for (int rr = 0; rr < 2; rr++) {
            const int gr = m0 + wm * 32 + mf * 16 + rr * 8 + g;
            if (gr < MTOT) {
                const int z = gr / D;
                const int i = gr - z * D;
                float* op = out + (size_t)z * HX_FEAT + XOFF + i
                          + (size_t)(nh * 128) * D;
                #pragma unroll
                for (int nf = 0; nf < 8; nf++) {
                    const int n = wn * 64 + nf * 8 + 2 * tg;
                    if (D == 1) {
                        float2 v;
                        v.x = c[mf][nf][rr * 2 + 0] * S;
                        v.y = c[mf][nf][rr * 2 + 1] * S;
                        *(float2*)(op + n) = v;
                    } else {
                        op[(size_t)n * D]       = c[mf][nf][rr * 2 + 0] * S;
                        op[(size_t)(n + 1) * D] = c[mf][nf][rr * 2 + 1] * S;
                    }
                }
            }
        }
    }
}

// ---------------------------------------------------------------------------
extern "C" void kernel_launch(void* const* d_in, const int* in_sizes, int n_in,
                              void* d_out, int out_size) {
    const float* feat = (const float*)d_in[0];
    const float* wt   = (const float*)d_in[1];
    float* out        = (float*)d_out;

    auto k1 = lin_k<1, 0,    0,      50000>;
    auto k3 = lin_k<3, 256,  65536,  150000>;
    auto k5 = lin_k<5, 1024, 131072, 250000>;

    cudaFuncSetAttribute(k1, cudaFuncAttributeMaxDynamicSharedMemorySize, SMEMB);
    cudaFuncSetAttribute(k3, cudaFuncAttributeMaxDynamicSharedMemorySize, SMEMB);
    cudaFuncSetAttribute(k5, cudaFuncAttributeMaxDynamicSharedMemorySize, SMEMB);

    k1<<<391 * 2,  NTH, SMEMB>>>(feat, wt, out);
    k3<<<1172 * 2, NTH, SMEMB>>>(feat, wt, out);
    k5<<<1954 * 2, NTH, SMEMB>>>(feat, wt, out);
}

// round 9
// speedup vs baseline: 1.3499x; 1.3499x over previous
#include <cuda_runtime.h>
#include <cstdint>

// ---------------------------------------------------------------------------
// Block-diagonal linear (256x0e+256x1o+256x2e): 3 GEMMs over rows (z,i):
//   A'[z*D+i][u] = feat[z, XOFF + u*D + i];  C = A' * W_b / 16.
// R9 = R7 skeleton (256-thr CTAs, 2/SM, tile 128x128, warp 32x64, cp.async
// native-layout A with 3-stage ring, 1 barrier/chunk) + fragment-order B:
// B staged LDG(frag-gather, L2-hot) -> cvt.rna -> STS.128; compute reads B
// as LDS.128 with no cvt. mma.sync m16n8k8 tf32.
// ---------------------------------------------------------------------------
#define HX_BZ   50000
#define HX_FEAT 2304

static constexpr int NTH = 256;   // 8 warps: wm = wid>>1 (4x32 rows), wn = wid&1

// ---------------------------------------------------------------------------
__device__ __forceinline__ uint32_t f2tf(float x) {
    uint32_t r;
    asm("cvt.rna.tf32.f32 %0, %1;" : "=r"(r) : "f"(x));
    return r;
}

__device__ __forceinline__ void mma8(float* c, const uint32_t* a,
                                     uint32_t b0, uint32_t b1) {
    asm volatile(
        "mma.sync.aligned.m16n8k8.row.col.f32.tf32.tf32.f32 "
        "{%0,%1,%2,%3}, {%4,%5,%6,%7}, {%8,%9}, {%0,%1,%2,%3};"
        : "+f"(c[0]), "+f"(c[1]), "+f"(c[2]), "+f"(c[3])
        : "r"(a[0]), "r"(a[1]), "r"(a[2]), "r"(a[3]), "r"(b0), "r"(b1));
}

#define CP_A16(dst, src, sz)                                               \
    asm volatile("cp.async.cg.shared.global [%0], [%1], 16, %2;"           \
                 :: "r"(dst), "l"(src), "r"(sz) : "memory")
#define CP_COMMIT() asm volatile("cp.async.commit_group;" ::: "memory")
#define CP_WAIT(n)  asm volatile("cp.async.wait_group %0;" :: "n"(n) : "memory")

__device__ __forceinline__ uint32_t smem_u32(const void* p) {
    uint32_t a;
    asm("{ .reg .u64 t; cvta.to.shared.u64 t, %1; cvt.u32.u64 %0, t; }"
        : "=r"(a) : "l"(p));
    return a;
}

// ---------------------------------------------------------------------------
template<int D, int XOFF, int WOFF, int MTOT>
__global__ void __launch_bounds__(NTH, 2)
lin_k(const float* __restrict__ feat, const float* __restrict__ wt,
      float* __restrict__ out)
{
    // A native layout: per z row, stride SD floats (conflict-aware padding)
    constexpr int SD   = (D == 1) ? 36 : (D == 3) ? 104 : 168;
    constexpr int NZ   = (D == 1) ? 128 : (D == 3) ? 44 : 27;
    constexpr int F4Z  = 8 * D;
    constexpr int TOT4 = NZ * F4Z;
    constexpr int PA   = (TOT4 + NTH - 1) / NTH;       // 4 / 5 / 5
    constexpr int ABUF = NZ * SD * 4;                  // bytes per A stage
    constexpr int BOFF = 3 * ABUF;                     // B after 3 A stages
    constexpr int BBUF = 16384;                        // 32k x 128n tf32

    extern __shared__ char smem[];
    const uint32_t smb = smem_u32(smem);

    const int tid  = threadIdx.x;
    const int lane = tid & 31;
    const int wid  = tid >> 5;
    const int g    = lane >> 2;
    const int tg   = lane & 3;
    const int wm   = wid >> 1;
    const int wn   = wid & 1;

    const int bid  = blockIdx.x;
    const int tile = bid >> 1;
    const int nh   = bid & 1;
    const int m0   = tile * 128;
    const int z0   = m0 / D;

    // ---- A staging decode (R7): PA float4 per thread ----
    const char* asrc[PA];
    uint32_t    adst[PA];
    uint32_t    aszr[PA];
    #pragma unroll
    for (int p = 0; p < PA; p++) {
        const int e  = tid + NTH * p;
        const int zr = e / F4Z;
        const int q  = e - zr * F4Z;
        const int z  = z0 + zr;
        const bool ok = (e < TOT4) && (z < HX_BZ);
        aszr[p] = ok ? 16u : 0u;
        asrc[p] = (const char*)(feat + (size_t)z * HX_FEAT + XOFF) + q * 16;
        adst[p] = (uint32_t)(zr * SD * 4 + q * 16);
        if (e >= TOT4) adst[p] = 0xFFFFFFFFu;
    }

    auto issueA = [&](int ch, int st) {
        const uint32_t sb0 = smb + st * ABUF;
        const int aoff = ch * (32 * D) * 4;
        #pragma unroll
        for (int p = 0; p < PA; p++)
            if (adst[p] != 0xFFFFFFFFu)
                CP_A16(sb0 + adst[p], asrc[p] + aoff, aszr[p]);
        CP_COMMIT();
    };

    // ---- B staging: frag-gather LDG -> cvt -> STS.128 ----
    uint32_t b_goff[4];
    #pragma unroll
    for (int p = 0; p < 4; p++) {
        const int e     = tid + NTH * p;
        const int l5    = e & 31;
        const int gg    = l5 >> 2, tt = l5 & 3;
        const int block = e >> 5;
        const int nfp   = block & 3;
        const int wnn   = (block >> 2) & 1;
        const int s     = block >> 3;
        const int k     = 8 * s + tt;
        const int n     = wnn * 64 + nfp * 16 + gg;
        b_goff[p] = (uint32_t)(k * 256 + n);
    }

    float rB[4][4];
    auto ldgB = [&](int ch) {
        const float* wp = wt + WOFF + nh * 128 + (size_t)ch * 32 * 256;
        #pragma unroll
        for (int p = 0; p < 4; p++) {
            const float* s = wp + b_goff[p];
            rB[p][0] = __ldg(s);
            rB[p][1] = __ldg(s + 1024);   // k+4
            rB[p][2] = __ldg(s + 8);      // n+8
            rB[p][3] = __ldg(s + 1032);
        }
    };

    auto stsB = [&](int st) {
        uint4* Bs = (uint4*)(smem + BOFF + st * BBUF);
        #pragma unroll
        for (int p = 0; p < 4; p++) {
            uint4 q;
            q.x = f2tf(rB[p][0]); q.y = f2tf(rB[p][1]);
            q.z = f2tf(rB[p][2]); q.w = f2tf(rB[p][3]);
            Bs[tid + NTH * p] = q;
        }
    };

    // ---- fragment row decode for A (once per tile) ----
    int arow[2][2];
    #pragma unroll
    for (int mf = 0; mf < 2; mf++)
        #pragma unroll
        for (int hh = 0; hh < 2; hh++) {
            const int r  = wm * 32 + mf * 16 + hh * 8 + g;
            const int gr = m0 + r;
            const int z  = gr / D;
            const int i  = gr - z * D;
            arow[mf][hh] = (z - z0) * SD + i;
        }
    const int tgD = tg * D;

    // ---- accumulators ----
    float c[2][8][4];
    #pragma unroll
    for (int mf = 0; mf < 2; mf++)
        #pragma unroll
        for (int nf = 0; nf < 8; nf++)
            #pragma unroll
            for (int q = 0; q < 4; q++) c[mf][nf][q] = 0.0f;

    auto compute = [&](int stA, int stB) {
        const float* Af = (const float*)(smem + stA * ABUF);
        const uint4* Bs = (const uint4*)(smem + BOFF + stB * BBUF);
        #pragma unroll
        for (int s = 0; s < 4; s++) {
            const int ks = 8 * s * D + tgD;
            uint32_t a[2][4];
            #pragma unroll
            for (int mf = 0; mf < 2; mf++) {
                a[mf][0] = f2tf(Af[arow[mf][0] + ks]);
                a[mf][1] = f2tf(Af[arow[mf][1] + ks]);
                a[mf][2] = f2tf(Af[arow[mf][0] + ks + 4 * D]);
                a[mf][3] = f2tf(Af[arow[mf][1] + ks + 4 * D]);
            }
            #pragma unroll
            for (int nfp = 0; nfp < 4; nfp++) {
                const uint4 b = Bs[((s * 2 + wn) * 4 + nfp) * 32 + lane];
                mma8(c[0][2 * nfp],     a[0], b.x, b.y);
                mma8(c[1][2 * nfp],     a[1], b.x, b.y);
                mma8(c[0][2 * nfp + 1], a[0], b.z, b.w);
                mma8(c[1][2 * nfp + 1], a[1], b.z, b.w);
            }
        }
    };

    // ---- pipeline: A 3-stage cp.async ring (depth-2), B reg-prefetch ----
    ldgB(0);
    issueA(0, 0);
    issueA(1, 1);
    stsB(0);
    ldgB(1);
    CP_WAIT(1);
    __syncthreads();

    #pragma unroll 1
    for (int ch = 0; ch < 8; ch++) {
        compute(ch % 3, ch & 1);
        if (ch < 7) {
            stsB((ch + 1) & 1);           // last reader (compute ch-1) done
            if (ch + 2 < 8) {
                issueA(ch + 2, (ch + 2) % 3);
                ldgB(ch + 2);
                CP_WAIT(1);               // A(ch+1) landed
            } else {
                CP_WAIT(0);
            }
            __syncthreads();
        }
    }

    // ---- epilogue: scatter rows (z,i), scale 1/sqrt(256) ----
    const float S = 0.0625f;
    #pragma unroll
    for (int mf = 0; mf < 2; mf++) {
        #pragma unroll
        for (int rr = 0; rr < 2; rr++) {
            const int gr = m0 + wm * 32 + mf * 16 + rr * 8 + g;
            if (gr < MTOT) {
                const int z = gr / D;
                const int i = gr - z * D;
                float* op = out + (size_t)z * HX_FEAT + XOFF + i
                          + (size_t)(nh * 128) * D;
                #pragma unroll
                for (int nf = 0; nf < 8; nf++) {
                    const int n = wn * 64 + nf * 8 + 2 * tg;
                    if (D == 1) {
                        float2 v;
                        v.x = c[mf][nf][rr * 2 + 0] * S;
                        v.y = c[mf][nf][rr * 2 + 1] * S;
                        *(float2*)(op + n) = v;
                    } else {
                        op[(size_t)n * D]       = c[mf][nf][rr * 2 + 0] * S;
                        op[(size_t)(n + 1) * D] = c[mf][nf][rr * 2 + 1] * S;
                    }
                }
            }
        }
    }
}

// ---------------------------------------------------------------------------
extern "C" void kernel_launch(void* const* d_in, const int* in_sizes, int n_in,
                              void* d_out, int out_size) {
    const float* feat = (const float*)d_in[0];
    const float* wt   = (const float*)d_in[1];
    float* out        = (float*)d_out;

    // smem = 3 A stages + 2 B stages
    constexpr int SM1 = 3 * (128 * 36 * 4)  + 2 * 16384;   // 88064
    constexpr int SM3 = 3 * (44 * 104 * 4)  + 2 * 16384;   // 87680
    constexpr int SM5 = 3 * (27 * 168 * 4)  + 2 * 16384;   // 87200

    auto k1 = lin_k<1, 0,    0,      50000>;
    auto k3 = lin_k<3, 256,  65536,  150000>;
    auto k5 = lin_k<5, 1024, 131072, 250000>;

    cudaFuncSetAttribute(k1, cudaFuncAttributeMaxDynamicSharedMemorySize, SM1);
    cudaFuncSetAttribute(k3, cudaFuncAttributeMaxDynamicSharedMemorySize, SM3);
    cudaFuncSetAttribute(k5, cudaFuncAttributeMaxDynamicSharedMemorySize, SM5);

    k1<<<391 * 2,  NTH, SM1>>>(feat, wt, out);
    k3<<<1172 * 2, NTH, SM3>>>(feat, wt, out);
    k5<<<1954 * 2, NTH, SM5>>>(feat, wt, out);
}

// round 10
// speedup vs baseline: 1.7474x; 1.2944x over previous
#include <cuda_runtime.h>
#include <cstdint>

// ---------------------------------------------------------------------------
// Block-diagonal linear (256x0e+256x1o+256x2e): 3 GEMMs over rows (z,i):
//   A'[z*D+i][u] = feat[z, XOFF + u*D + i];  C = A' * W_b / 16.
// R10 = R7 skeleton + weight prepass: a tiny kernel converts (cvt.rna tf32)
// and PRE-FRAGMENTS all weights into a __device__ scratch in the exact
// per-chunk fragment order the MMA consumes. Main kernel cp.asyncs B frag
// tiles contiguously and reads them with LDS.128 (no cvt, no gather).
// A path: cp.async native layout, scalar frag LDS + cvt (R7-proven).
// mma.sync m16n8k8 tf32 (PTX targets compute_103; tcgen05 unavailable).
// ---------------------------------------------------------------------------
#define HX_BZ   50000
#define HX_FEAT 2304

static constexpr int NTH = 256;   // 8 warps: wm = wid>>1 (4x32 rows), wn = wid&1

// pre-fragmented weights: [b*2+nh][ch][1024 uint4]  (3*2*8*1024 = 49152)
__device__ uint4 g_wfrag[49152];

// ---------------------------------------------------------------------------
__device__ __forceinline__ uint32_t f2tf(float x) {
    uint32_t r;
    asm("cvt.rna.tf32.f32 %0, %1;" : "=r"(r) : "f"(x));
    return r;
}

__device__ __forceinline__ void mma8(float* c, const uint32_t* a,
                                     uint32_t b0, uint32_t b1) {
    asm volatile(
        "mma.sync.aligned.m16n8k8.row.col.f32.tf32.tf32.f32 "
        "{%0,%1,%2,%3}, {%4,%5,%6,%7}, {%8,%9}, {%0,%1,%2,%3};"
        : "+f"(c[0]), "+f"(c[1]), "+f"(c[2]), "+f"(c[3])
        : "r"(a[0]), "r"(a[1]), "r"(a[2]), "r"(a[3]), "r"(b0), "r"(b1));
}

#define CP_A16(dst, src, sz)                                               \
    asm volatile("cp.async.cg.shared.global [%0], [%1], 16, %2;"           \
                 :: "r"(dst), "l"(src), "r"(sz) : "memory")
#define CP_COMMIT() asm volatile("cp.async.commit_group;" ::: "memory")
#define CP_WAIT(n)  asm volatile("cp.async.wait_group %0;" :: "n"(n) : "memory")

__device__ __forceinline__ uint32_t smem_u32(const void* p) {
    uint32_t a;
    asm("{ .reg .u64 t; cvta.to.shared.u64 t, %1; cvt.u32.u64 %0, t; }"
        : "=r"(a) : "l"(p));
    return a;
}

// ---------------------------------------------------------------------------
// Prepass: fragment-order + tf32-round all weights (once, ~3us).
// e decode matches the main kernel's B LDS pattern:
//   l5 = e&31 -> gg = l5>>2, tt = l5&3;  blk = e>>5 -> nfp, wnn, s
//   k = 32ch + 8s + tt,  n = 128nh + 64wnn + 16nfp + gg
//   uint4 = { W[k][n], W[k+4][n], W[k][n+8], W[k+4][n+8] }
__global__ void prep_w(const float* __restrict__ wt) {
    const int t = blockIdx.x * blockDim.x + threadIdx.x;
    if (t >= 49152) return;
    const int e  = t & 1023;
    const int ch = (t >> 10) & 7;
    const int bn = t >> 13;              // b*2 + nh
    const int b  = bn >> 1, nh = bn & 1;
    const int woff = (b == 0) ? 0 : (b == 1) ? 65536 : 131072;
    const int l5 = e & 31, gg = l5 >> 2, tt = l5 & 3;
    const int blk = e >> 5, nfp = blk & 3, wnn = (blk >> 2) & 1, s = blk >> 3;
    const int k = 32 * ch + 8 * s + tt;
    const int n = 128 * nh + 64 * wnn + 16 * nfp + gg;
    const float* wp = wt + woff + k * 256 + n;
    uint4 q;
    q.x = f2tf(wp[0]);
    q.y = f2tf(wp[1024]);   // k+4
    q.z = f2tf(wp[8]);      // n+8
    q.w = f2tf(wp[1032]);
    g_wfrag[t] = q;
}

// ---------------------------------------------------------------------------
template<int D, int XOFF, int MTOT>
__global__ void __launch_bounds__(NTH, 2)
lin_k(const float* __restrict__ feat, float* __restrict__ out)
{
    // A native layout: per z row, stride SD floats (conflict-aware padding)
    constexpr int SD   = (D == 1) ? 36 : (D == 3) ? 104 : 168;
    constexpr int NZ   = (D == 1) ? 128 : (D == 3) ? 44 : 27;
    constexpr int F4Z  = 8 * D;
    constexpr int TOT4 = NZ * F4Z;
    constexpr int PA   = (TOT4 + NTH - 1) / NTH;       // 4 / 5 / 5
    constexpr int ABUF = NZ * SD * 4;                  // bytes per A stage
    constexpr int BOFF = 3 * ABUF;
    constexpr int BBUF = 16384;                        // one frag B chunk

    extern __shared__ char smem[];
    const uint32_t smb = smem_u32(smem);

    const int tid  = threadIdx.x;
    const int lane = tid & 31;
    const int wid  = tid >> 5;
    const int g    = lane >> 2;
    const int tg   = lane & 3;
    const int wm   = wid >> 1;
    const int wn   = wid & 1;

    const int bid  = blockIdx.x;
    const int tile = bid >> 1;
    const int nh   = bid & 1;
    const int m0   = tile * 128;
    const int z0   = m0 / D;

    // B frag source (contiguous per chunk)
    const int bsel = ((D == 1) ? 0 : (D == 3) ? 2 : 4) + nh;  // b*2+nh
    const char* bbase = (const char*)(g_wfrag + bsel * 8192);

    // ---- A staging decode: PA float4 per thread ----
    const char* asrc[PA];
    uint32_t    adst[PA];
    uint32_t    aszr[PA];
    #pragma unroll
    for (int p = 0; p < PA; p++) {
        const int e  = tid + NTH * p;
        const int zr = e / F4Z;
        const int q  = e - zr * F4Z;
        const int z  = z0 + zr;
        const bool ok = (e < TOT4) && (z < HX_BZ);
        aszr[p] = ok ? 16u : 0u;
        asrc[p] = (const char*)(feat + (size_t)z * HX_FEAT + XOFF) + q * 16;
        adst[p] = (uint32_t)(zr * SD * 4 + q * 16);
        if (e >= TOT4) adst[p] = 0xFFFFFFFFu;
    }

    // one commit group per chunk: A (native) + B (frag, contiguous)
    auto issue = [&](int ch, int st) {
        const uint32_t sa0 = smb + st * ABUF;
        const int aoff = ch * (32 * D) * 4;
        #pragma unroll
        for (int p = 0; p < PA; p++)
            if (adst[p] != 0xFFFFFFFFu)
                CP_A16(sa0 + adst[p], asrc[p] + aoff, aszr[p]);
        const uint32_t sb0 = smb + BOFF + st * BBUF + tid * 16;
        const char* bsrc = bbase + ch * BBUF + tid * 16;
        #pragma unroll
        for (int p = 0; p < 4; p++)
            CP_A16(sb0 + p * (NTH * 16), bsrc + p * (NTH * 16), 16u);
        CP_COMMIT();
    };

    // ---- fragment row decode for A (once per tile) ----
    int arow[2][2];
    #pragma unroll
    for (int mf = 0; mf < 2; mf++)
        #pragma unroll
        for (int hh = 0; hh < 2; hh++) {
            const int r  = wm * 32 + mf * 16 + hh * 8 + g;
            const int gr = m0 + r;
            const int z  = gr / D;
            const int i  = gr - z * D;
            arow[mf][hh] = (z - z0) * SD + i;
        }
    const int tgD = tg * D;

    // ---- accumulators ----
    float c[2][8][4];
    #pragma unroll
    for (int mf = 0; mf < 2; mf++)
        #pragma unroll
        for (int nf = 0; nf < 8; nf++)
            #pragma unroll
            for (int q = 0; q < 4; q++) c[mf][nf][q] = 0.0f;

    auto compute = [&](int st) {
        const float* Af = (const float*)(smem + st * ABUF);
        const uint4* Bs = (const uint4*)(smem + BOFF + st * BBUF);
        #pragma unroll
        for (int s = 0; s < 4; s++) {
            const int ks = 8 * s * D + tgD;
            uint32_t a[2][4];
            #pragma unroll
            for (int mf = 0; mf < 2; mf++) {
                a[mf][0] = f2tf(Af[arow[mf][0] + ks]);
                a[mf][1] = f2tf(Af[arow[mf][1] + ks]);
                a[mf][2] = f2tf(Af[arow[mf][0] + ks + 4 * D]);
                a[mf][3] = f2tf(Af[arow[mf][1] + ks + 4 * D]);
            }
            #pragma unroll
            for (int nfp = 0; nfp < 4; nfp++) {
                const uint4 b = Bs[((s * 2 + wn) * 4 + nfp) * 32 + lane];
                mma8(c[0][2 * nfp],     a[0], b.x, b.y);
                mma8(c[1][2 * nfp],     a[1], b.x, b.y);
                mma8(c[0][2 * nfp + 1], a[0], b.z, b.w);
                mma8(c[1][2 * nfp + 1], a[1], b.z, b.w);
            }
        }
    };

    // ---- pipeline: joint 3-stage ring, depth-2 prefetch, 1 barrier/chunk --
    issue(0, 0);
    issue(1, 1);
    CP_WAIT(1);
    __syncthreads();

    #pragma unroll 1
    for (int ch = 0; ch < 8; ch++) {
        compute(ch % 3);
        if (ch < 7) {
            if (ch + 2 < 8) {
                issue(ch + 2, (ch + 2) % 3);
                CP_WAIT(1);
            } else {
                CP_WAIT(0);
            }
            __syncthreads();
        }
    }

    // ---- epilogue: scatter rows (z,i), scale 1/sqrt(256) ----
    const float S = 0.0625f;
    #pragma unroll
    for (int mf = 0; mf < 2; mf++) {
        #pragma unroll
        for (int rr = 0; rr < 2; rr++) {
            const int gr = m0 + wm * 32 + mf * 16 + rr * 8 + g;
            if (gr < MTOT) {
                const int z = gr / D;
                const int i = gr - z * D;
                float* op = out + (size_t)z * HX_FEAT + XOFF + i
                          + (size_t)(nh * 128) * D;
                #pragma unroll
                for (int nf = 0; nf < 8; nf++) {
                    const int n = wn * 64 + nf * 8 + 2 * tg;
                    if (D == 1) {
                        float2 v;
                        v.x = c[mf][nf][rr * 2 + 0] * S;
                        v.y = c[mf][nf][rr * 2 + 1] * S;
                        *(float2*)(op + n) = v;
                    } else {
                        op[(size_t)n * D]       = c[mf][nf][rr * 2 + 0] * S;
                        op[(size_t)(n + 1) * D] = c[mf][nf][rr * 2 + 1] * S;
                    }
                }
            }
        }
    }
}

// ---------------------------------------------------------------------------
extern "C" void kernel_launch(void* const* d_in, const int* in_sizes, int n_in,
                              void* d_out, int out_size) {
    const float* feat = (const float*)d_in[0];
    const float* wt   = (const float*)d_in[1];
    float* out        = (float*)d_out;

    // smem = 3 x (A stage + B frag stage)
    constexpr int SM1 = 3 * (128 * 36 * 4) + 3 * 16384;   // 104448
    constexpr int SM3 = 3 * (44 * 104 * 4) + 3 * 16384;   // 104064
    constexpr int SM5 = 3 * (27 * 168 * 4) + 3 * 16384;   // 103584

    auto k1 = lin_k<1, 0,    50000>;
    auto k3 = lin_k<3, 256,  150000>;
    auto k5 = lin_k<5, 1024, 250000>;

    cudaFuncSetAttribute(k1, cudaFuncAttributeMaxDynamicSharedMemorySize, SM1);
    cudaFuncSetAttribute(k3, cudaFuncAttributeMaxDynamicSharedMemorySize, SM3);
    cudaFuncSetAttribute(k5, cudaFuncAttributeMaxDynamicSharedMemorySize, SM5);

    prep_w<<<192, 256>>>(wt);                 // 49152 threads
    k1<<<391 * 2,  NTH, SM1>>>(feat, out);
    k3<<<1172 * 2, NTH, SM3>>>(feat, out);
    k5<<<1954 * 2, NTH, SM5>>>(feat, out);
}